// round 11
// baseline (speedup 1.0000x reference)
#include <cuda_runtime.h>
#include <cuda_fp16.h>
#include <cstdint>

// Problem constants
#define BB 32
#define CC 256
#define HH 32
#define WW 32
#define KK 1024
#define NN 1024                      // H*W
#define ZP_BATCH (CC * NN)           // 262144 floats per batch
#define ZQ_SIZE (BB * CC * HH * WW)  // 8388608
#define IDX_SIZE (BB * NN)           // 32768

// ---------------- k_mma smem layout (u32 units) ----------------
// A hi [128 n][132]  @ 0          (row = 128 u32 data + 4 pad)
// A lo               @ OFF_AL
// E bufs [2 buf][hi/lo][128 k][20] @ OFF_EB  (row = 16 u32 data + 4 pad)
// e2s float[1024]    @ OFF_E2
#define OFF_AH 0
#define OFF_AL 16896
#define OFF_EB 33792
#define EB_SEG 2560
#define OFF_E2 44032
#define SMEM_U32 45056
#define SMEM_MMA_BYTES (SMEM_U32 * 4)   // 180224

#define INV2048 4.8828125e-4f

// Device scratch (allocation-free rule: __device__ globals)
__device__ float g_zp[BB * ZP_BATCH];   // contiguous [b][h][w][c] image of z_p
__device__ float g_e2[KK];
__device__ float g_z2[BB * NN];         // view-column norms
__device__ int   g_idx[BB * NN];
__device__ float g_losspart[1024];
// pre-split fp16 operands
__device__ __align__(16) __half g_eh[KK * CC];          // E hi halves [k][c]
__device__ __align__(16) __half g_el[KK * CC];          // E lo halves
__device__ __align__(16) __half g_zh[BB * NN * CC];     // A hi halves [b][n][c] (view rows)
__device__ __align__(16) __half g_zl[BB * NN * CC];     // A lo halves

// ---------- helpers ----------
__device__ __forceinline__ __half lo_split(float x, __half h) {
    return __float2half_rn((x - __half2float(h)) * 2048.0f);
}
__device__ __forceinline__ uint32_t smem_u32(const void* p) {
    uint32_t a;
    asm("{ .reg .u64 t; cvta.to.shared.u64 t, %1; cvt.u32.u64 %0, t; }" : "=r"(a) : "l"(p));
    return a;
}
__device__ __forceinline__ void ldsm4(uint32_t* r, uint32_t addr) {
    asm volatile("ldmatrix.sync.aligned.m8n8.x4.shared.b16 {%0,%1,%2,%3}, [%4];"
                 : "=r"(r[0]), "=r"(r[1]), "=r"(r[2]), "=r"(r[3]) : "r"(addr));
}
__device__ __forceinline__ void mma_f16(float* d, const uint32_t* a,
                                        uint32_t b0, uint32_t b1) {
    asm volatile(
        "mma.sync.aligned.m16n8k16.row.col.f32.f16.f16.f32 "
        "{%0,%1,%2,%3}, {%4,%5,%6,%7}, {%8,%9}, {%0,%1,%2,%3};"
        : "+f"(d[0]), "+f"(d[1]), "+f"(d[2]), "+f"(d[3])
        : "r"(a[0]), "r"(a[1]), "r"(a[2]), "r"(a[3]), "r"(b0), "r"(b1));
}

// ---------- kernel 1: e2[k] + pre-split E halves ----------
__global__ void k_e2(const float* __restrict__ E) {
    int warp = threadIdx.x >> 5, lane = threadIdx.x & 31;
    int k = blockIdx.x * 8 + warp;
    const float* row = E + k * CC;
    float v[8];
    float s = 0.f;
#pragma unroll
    for (int i = 0; i < 8; i++) { v[i] = row[lane + 32 * i]; s = fmaf(v[i], v[i], s); }
#pragma unroll
    for (int o = 16; o; o >>= 1) s += __shfl_xor_sync(0xFFFFFFFFu, s, o);
    if (lane == 0) g_e2[k] = s;
#pragma unroll
    for (int i = 0; i < 8; i++) {
        int c = lane + 32 * i;
        __half hv = __float2half_rn(v[i]);
        g_eh[k * CC + c] = hv;
        g_el[k * CC + c] = lo_split(v[i], hv);
    }
}

// ---------- kernel 2: transpose z -> g_zp, and emit A-row halves ----------
__global__ void k_tr(const float* __restrict__ z) {
    __shared__ float s[CC][33];
    int b = blockIdx.x >> 5, h = blockIdx.x & 31;
    int w = threadIdx.x & 31, t8 = threadIdx.x >> 5;
    const float* zp = z + ((long long)(b * CC) * HH + h) * WW + w;
#pragma unroll
    for (int i = 0; i < 32; i++) {
        int c = t8 * 32 + i;
        s[c][w] = zp[(long long)c * HH * WW];
    }
    __syncthreads();
    float* out = g_zp + (long long)b * ZP_BATCH + h * (WW * CC);
#pragma unroll
    for (int i = 0; i < 32; i++) {
        int f = threadIdx.x + i * 256;
        int c = f & 255, ww = f >> 8;
        out[f] = s[c][ww];
    }
    // A(n, 8h+c') = flat[(8h+c')*1024 + n] = s[n & 255][c'*4 + (n>>8)]
    int tid = threadIdx.x;
#pragma unroll
    for (int i = 0; i < 4; i++) {
        int n = i * 256 + tid;
        __align__(16) __half hh[8], ll[8];
#pragma unroll
        for (int cp = 0; cp < 8; cp++) {
            float v = s[tid][cp * 4 + i];
            __half hv = __float2half_rn(v);
            hh[cp] = hv;
            ll[cp] = lo_split(v, hv);
        }
        long long off = ((long long)b * NN + n) * CC + h * 8;
        *(uint4*)&g_zh[off] = *(uint4*)hh;
        *(uint4*)&g_zl[off] = *(uint4*)ll;
    }
}

// ---------- kernel 3: z2[b][n] over the REINTERPRETED [256,1024] view ----------
__global__ void k_z2() {
    int b = blockIdx.x >> 2;
    int n = (blockIdx.x & 3) * 256 + threadIdx.x;
    const float* base = g_zp + (long long)b * ZP_BATCH + n;
    float s = 0.f;
#pragma unroll 8
    for (int i = 0; i < CC; i++) { float v = base[i * NN]; s = fmaf(v, v, s); }
    g_z2[b * NN + n] = s;
}

// ---------- kernel 4: fp16 2-split mma.sync + ldmatrix + argmin ----------
// Warp (wr = w>>3, wp = w&7): A rows [16wp,16wp+16), codes [wr*64, wr*64+64).
__global__ void __launch_bounds__(512, 1) k_mma(float* __restrict__ dout, int out_size) {
    extern __shared__ uint32_t smu[];
    float* e2s = (float*)(smu + OFF_E2);
    uint32_t sb = smem_u32(smu);

    int tid = threadIdx.x;
    int w = tid >> 5, lane = tid & 31;
    int g = lane >> 2, t = lane & 3;
    int wr = w >> 3, wp = w & 7;
    int b = blockIdx.x >> 3;
    int n0 = (blockIdx.x & 7) * 128;

    // ---- A panel copy (pre-split halves, padded rows) ----
    {
        const __half* zh = g_zh + ((long long)b * NN + n0) * CC;
        const __half* zl = g_zl + ((long long)b * NN + n0) * CC;
#pragma unroll
        for (int i = 0; i < 8; i++) {
            int unit = tid + 512 * i;
            int r = unit >> 5, j = unit & 31;
            *(uint4*)(smu + OFF_AH + r * 132 + j * 4) = *(const uint4*)(zh + r * 256 + j * 8);
            *(uint4*)(smu + OFF_AL + r * 132 + j * 4) = *(const uint4*)(zl + r * 256 + j * 8);
        }
    }
    for (int i = tid; i < KK; i += 512) e2s[i] = g_e2[i];

    // ---- E staging roles: thread = (k-row, 16B quarter) ----
    int ekr = tid >> 2, eq = tid & 3;
    uint4 ph = *(const uint4*)(g_eh + ekr * 256 + eq * 8);     // chunk 0
    uint4 pl = *(const uint4*)(g_el + ekr * 256 + eq * 8);
    *(uint4*)(smu + OFF_EB + ekr * 20 + eq * 4) = ph;
    *(uint4*)(smu + OFF_EB + EB_SEG + ekr * 20 + eq * 4) = pl;

    // ---- frag addresses (bytes) ----
    uint32_t a_row = (uint32_t)((wp * 16 + (lane & 15)) * 132 + (lane >> 4) * 4);
    uint32_t aaddr_h = sb + (OFF_AH + a_row) * 4;
    uint32_t aaddr_l = sb + (OFF_AL + a_row) * 4;
    uint32_t b_row = (uint32_t)((wr * 64 + (lane & 7) + ((lane >> 4) & 1) * 8) * 20
                                + ((lane >> 3) & 1) * 4);

    int p0 = wp * 16 + g, p1 = p0 + 8;
    float z2a = g_z2[b * NN + n0 + p0];
    float z2b = g_z2[b * NN + n0 + p1];
    float bv0 = 3.4e38f, bv1 = 3.4e38f;
    int   bk0 = 0, bk1 = 0;
    __syncthreads();

    float acc_hh[8][4], acc_lo[8][4];

    for (int q = 0; q < 64; q++) {             // chunk: k-slab q>>3, c-range (q&7)*32
        int buf = q & 1, ch = q & 7;
        if (ch == 0) {
#pragma unroll
            for (int nf = 0; nf < 8; nf++)
#pragma unroll
                for (int j = 0; j < 4; j++) { acc_hh[nf][j] = 0.f; acc_lo[nf][j] = 0.f; }
        }
        if (q + 1 < 64) {
            int nk0 = ((q + 1) >> 3) * 128, nc0 = ((q + 1) & 7) * 32;
            const __half* eh = g_eh + (nk0 + ekr) * 256 + nc0 + eq * 8;
            const __half* el = g_el + (nk0 + ekr) * 256 + nc0 + eq * 8;
            ph = *(const uint4*)eh;
            pl = *(const uint4*)el;
        }

        uint32_t ebase = sb + (OFF_EB + (buf * 2) * EB_SEG) * 4;
#pragma unroll
        for (int s = 0; s < 2; s++) {
            uint32_t ah[4], al[4];
            // A c-offset: chunk ch*32 halves (64 B) + s*16 halves (32 B)
            ldsm4(ah, aaddr_h + ch * 64 + s * 32);
            ldsm4(al, aaddr_l + ch * 64 + s * 32);
#pragma unroll
            for (int nfp = 0; nfp < 4; nfp++) {
                uint32_t baddr = ebase + (b_row + nfp * 320) * 4 + s * 32;
                uint32_t bh[4], bl[4];
                ldsm4(bh, baddr);
                ldsm4(bl, baddr + EB_SEG * 4);
                int nf0 = nfp * 2, nf1 = nf0 + 1;
                mma_f16(acc_hh[nf0], ah, bh[0], bh[1]);
                mma_f16(acc_hh[nf1], ah, bh[2], bh[3]);
                mma_f16(acc_lo[nf0], ah, bl[0], bl[1]);
                mma_f16(acc_lo[nf1], ah, bl[2], bl[3]);
                mma_f16(acc_lo[nf0], al, bh[0], bh[1]);
                mma_f16(acc_lo[nf1], al, bh[2], bh[3]);
            }
        }

        if (ch == 7) {                          // half-slab done: fold argmin
            int k0 = (q >> 3) * 128;
#pragma unroll
            for (int nf = 0; nf < 8; nf++) {
                int ka = k0 + wr * 64 + nf * 8 + 2 * t;
                float e2a = e2s[ka], e2b = e2s[ka + 1];
                float dot0 = fmaf(acc_lo[nf][0], INV2048, acc_hh[nf][0]);
                float dot1 = fmaf(acc_lo[nf][1], INV2048, acc_hh[nf][1]);
                float dot2 = fmaf(acc_lo[nf][2], INV2048, acc_hh[nf][2]);
                float dot3 = fmaf(acc_lo[nf][3], INV2048, acc_hh[nf][3]);
                float d0 = (e2a + z2a) - 2.0f * dot0;
                float d1 = (e2b + z2a) - 2.0f * dot1;
                float d2 = (e2a + z2b) - 2.0f * dot2;
                float d3 = (e2b + z2b) - 2.0f * dot3;
                if (d0 < bv0 || (d0 == bv0 && ka     < bk0)) { bv0 = d0; bk0 = ka; }
                if (d1 < bv0 || (d1 == bv0 && ka + 1 < bk0)) { bv0 = d1; bk0 = ka + 1; }
                if (d2 < bv1 || (d2 == bv1 && ka     < bk1)) { bv1 = d2; bk1 = ka; }
                if (d3 < bv1 || (d3 == bv1 && ka + 1 < bk1)) { bv1 = d3; bk1 = ka + 1; }
            }
        }

        if (q + 1 < 64) {
            uint32_t nb = (uint32_t)((buf ^ 1) * 2) * EB_SEG;
            *(uint4*)(smu + OFF_EB + nb + ekr * 20 + eq * 4) = ph;
            *(uint4*)(smu + OFF_EB + nb + EB_SEG + ekr * 20 + eq * 4) = pl;
        }
        __syncthreads();
    }

    // reduce over the 4 lanes of each group (lexicographic, first-k preference)
#pragma unroll
    for (int off = 1; off <= 2; off <<= 1) {
        float ov0 = __shfl_xor_sync(0xFFFFFFFFu, bv0, off);
        int   ok0 = __shfl_xor_sync(0xFFFFFFFFu, bk0, off);
        float ov1 = __shfl_xor_sync(0xFFFFFFFFu, bv1, off);
        int   ok1 = __shfl_xor_sync(0xFFFFFFFFu, bk1, off);
        if (ov0 < bv0 || (ov0 == bv0 && ok0 < bk0)) { bv0 = ov0; bk0 = ok0; }
        if (ov1 < bv1 || (ov1 == bv1 && ok1 < bk1)) { bv1 = ov1; bk1 = ok1; }
    }

    // cross-warp-row combine via smem (A panel dead; reuse)
    float* rval = (float*)smu;            // [2][128]
    int*   ridx = (int*)(smu + 256);      // [2][128]
    __syncthreads();
    if (t == 0) {
        rval[wr * 128 + p0] = bv0; ridx[wr * 128 + p0] = bk0;
        rval[wr * 128 + p1] = bv1; ridx[wr * 128 + p1] = bk1;
    }
    __syncthreads();
    if (tid < 128) {
        float v0 = rval[tid];       int k0i = ridx[tid];
        float v1 = rval[128 + tid]; int k1i = ridx[128 + tid];
        int bk;
        if (v1 < v0 || (v1 == v0 && k1i < k0i)) bk = k1i; else bk = k0i;
        int n = n0 + tid;
        g_idx[b * NN + n] = bk;
        long long off = (long long)ZQ_SIZE + b * NN + n;
        if (off < (long long)out_size) dout[off] = (float)bk;
    }
}

// ---------- kernel 5: gather z_q (STE-exact), loss partials ----------
__global__ void k_gather(const float* __restrict__ z, const float* __restrict__ E,
                         float* __restrict__ dout) {
    __shared__ float srow[32 * 257];
    __shared__ int   skid[32];
    __shared__ float sw[8];
    int b = blockIdx.x >> 5, h = blockIdx.x & 31;
    int tid = threadIdx.x;
    int warp = tid >> 5, lane = tid & 31;

    if (tid < 32) skid[tid] = g_idx[b * NN + h * WW + tid];
    __syncthreads();

#pragma unroll
    for (int r2 = 0; r2 < 4; r2++) {
        int r = warp * 4 + r2;
        const float* er = E + skid[r] * CC;
#pragma unroll
        for (int i = 0; i < 8; i++)
            srow[r * 257 + lane + 32 * i] = er[lane + 32 * i];
    }
    __syncthreads();

    int w = lane;
    float local = 0.f;
#pragma unroll 4
    for (int s = 0; s < 32; s++) {
        int c = warp * 32 + s;
        long long zoff = ((long long)(b * CC + c) * HH + h) * WW + w;
        float zv = z[zoff];
        float eq = srow[w * 257 + c];
        float d = eq - zv;
        local = fmaf(d, d, local);
        dout[zoff] = zv + (eq - zv);   // exact straight-through arithmetic
    }
#pragma unroll
    for (int o = 16; o; o >>= 1) local += __shfl_xor_sync(0xFFFFFFFFu, local, o);
    if (lane == 0) sw[warp] = local;
    __syncthreads();
    if (tid == 0) {
        float s2 = 0.f;
#pragma unroll
        for (int i = 0; i < 8; i++) s2 += sw[i];
        g_losspart[blockIdx.x] = s2;
    }
}

// ---------- kernel 6: deterministic loss finalize ----------
__global__ void k_final(float* __restrict__ dout, int out_size) {
    __shared__ float smf[256];
    float s = 0.f;
    for (int i = threadIdx.x; i < 1024; i += 256) s += g_losspart[i];
    smf[threadIdx.x] = s;
    __syncthreads();
    if (threadIdx.x == 0) {
        float t = 0.f;
        for (int i = 0; i < 256; i++) t += smf[i];
        float m = t / 8388608.0f;
        float loss = m + 0.25f * m;
        long long off = (long long)ZQ_SIZE + IDX_SIZE;
        if (off < (long long)out_size) dout[off] = loss;
    }
}

extern "C" void kernel_launch(void* const* d_in, const int* in_sizes, int n_in,
                              void* d_out, int out_size) {
    const float* z = (const float*)d_in[0];
    const float* E = (const float*)d_in[1];
    float* out = (float*)d_out;

    cudaFuncSetAttribute(k_mma, cudaFuncAttributeMaxDynamicSharedMemorySize, SMEM_MMA_BYTES);

    k_e2<<<128, 256>>>(E);
    k_tr<<<1024, 256>>>(z);
    k_z2<<<128, 256>>>();
    k_mma<<<256, 512, SMEM_MMA_BYTES>>>(out, out_size);
    if (out_size >= ZQ_SIZE) k_gather<<<1024, 256>>>(z, E, out);
    k_final<<<1, 256>>>(out, out_size);
}